// round 12
// baseline (speedup 1.0000x reference)
#include <cuda_runtime.h>
#include <cstdint>

// Problem constants (fixed by dataset): B=1, N=4096, C=8, H=W=128, K=8
#define MAXN 8192
constexpr float RADIUS = 0.05f;
constexpr int H = 128, W = 128, C = 8, K = 8;
constexpr int TILE = 8;             // 8x8 pixel tiles
constexpr int TX = W / TILE;        // 16
constexpr int TY = H / TILE;        // 16
constexpr int NTILES = TX * TY;     // 256 CTAs
constexpr int PIX = TILE * TILE;    // 64 pixels per tile
constexpr int SPLIT = 8;            // threads per pixel in scan phase
constexpr int TPB = PIX * SPLIT;    // 512 threads per CTA
constexpr int QCAP = 192;           // per-quadrant cap (mean ~27)
constexpr int PIXCAP = 40;          // per-pixel hit cap (mean ~8)

// smem: quadrant lists 4*192*16 = 12288 B; hit lists 64*40*12 = 30720 B -> 43008 B
constexpr int RAWSZ = 4 * QCAP * 16 + PIX * PIXCAP * 12;

__global__ void __launch_bounds__(TPB)
render_kernel(const float* __restrict__ pts,
              const float* __restrict__ feat,
              float* __restrict__ out, int n) {
    __shared__ __align__(16) unsigned char raw[RAWSZ];
    float4* s_quad = (float4*)raw;                                  // [4][QCAP]
    float*  s_hz   = (float*)(raw + 4 * QCAP * 16);                 // [64][40]
    float*  s_hd   = (float*)(raw + 4 * QCAP * 16 + PIX * PIXCAP * 4);
    int*    s_hi   = (int*)  (raw + 4 * QCAP * 16 + PIX * PIXCAP * 8);
    __shared__ int s_qcnt[4];
    __shared__ int s_pixcnt[PIX];

    const int tile = blockIdx.x;
    const int tx = tile & (TX - 1);
    const int ty = tile >> 4;
    const int tid = threadIdx.x;

    if (tid < PIX) s_pixcnt[tid] = 0;
    if (tid < 4)   s_qcnt[tid] = 0;
    __syncthreads();

    // ---- bboxes over pixel centers, expanded by splat radius + eps (NDC) ----
    const float EPS = 1e-5f;
    const float x0 = ((float)(tx * TILE)            + 0.5f) * (2.0f / W) - 1.0f - RADIUS - EPS;
    const float x1 = ((float)(tx * TILE + TILE - 1) + 0.5f) * (2.0f / W) - 1.0f + RADIUS + EPS;
    const float y0 = ((float)(ty * TILE)            + 0.5f) * (2.0f / H) - 1.0f - RADIUS - EPS;
    const float y1 = ((float)(ty * TILE + TILE - 1) + 0.5f) * (2.0f / H) - 1.0f + RADIUS + EPS;

    float qx0[2], qx1[2], qy0[2], qy1[2];
    #pragma unroll
    for (int hf = 0; hf < 2; hf++) {
        qx0[hf] = ((float)(tx * TILE + hf * 4)     + 0.5f) * (2.0f / W) - 1.0f - RADIUS - EPS;
        qx1[hf] = ((float)(tx * TILE + hf * 4 + 3) + 0.5f) * (2.0f / W) - 1.0f + RADIUS + EPS;
        qy0[hf] = ((float)(ty * TILE + hf * 4)     + 0.5f) * (2.0f / H) - 1.0f - RADIUS - EPS;
        qy1[hf] = ((float)(ty * TILE + hf * 4 + 3) + 0.5f) * (2.0f / H) - 1.0f + RADIUS + EPS;
    }

    // ---- Phase 1: cull all points vs tile bbox (division-free), vectorized
    //      loads: thread t owns points [8t, 8t+8) = 6 aligned float4 ---------
    {
        const int base = tid * 8;
        float xs[8], ys[8], zs[8];
        int npts = 0;
        if (base + 8 <= n) {
            const float4* p4 = (const float4*)pts + tid * 6;
            float4 v0 = __ldg(&p4[0]);
            float4 v1 = __ldg(&p4[1]);
            float4 v2 = __ldg(&p4[2]);
            float4 v3 = __ldg(&p4[3]);
            float4 v4 = __ldg(&p4[4]);
            float4 v5 = __ldg(&p4[5]);
            xs[0] = v0.x; ys[0] = v0.y; zs[0] = v0.z;
            xs[1] = v0.w; ys[1] = v1.x; zs[1] = v1.y;
            xs[2] = v1.z; ys[2] = v1.w; zs[2] = v2.x;
            xs[3] = v2.y; ys[3] = v2.z; zs[3] = v2.w;
            xs[4] = v3.x; ys[4] = v3.y; zs[4] = v3.z;
            xs[5] = v3.w; ys[5] = v4.x; zs[5] = v4.y;
            xs[6] = v4.z; ys[6] = v4.w; zs[6] = v5.x;
            xs[7] = v5.y; ys[7] = v5.z; zs[7] = v5.w;
            npts = 8;
        } else if (base < n) {           // scalar tail (unused for n=4096)
            npts = n - base;
            for (int k = 0; k < npts; k++) {
                xs[k] = pts[3 * (base + k) + 0];
                ys[k] = pts[3 * (base + k) + 1];
                zs[k] = pts[3 * (base + k) + 2];
            }
        }
        #pragma unroll
        for (int k = 0; k < 8; k++) {
            if (k < npts) {
                float x = xs[k], y = ys[k], z = zs[k];
                // z>0: x/z >= x0  <=>  x >= x0*z (conservative; exact test later)
                bool hit = (z > 0.0f) &&
                           (x >= x0 * z) && (x <= x1 * z) &&
                           (y >= y0 * z) && (y <= y1 * z);
                if (hit) {
                    float px = x / z;      // exact IEEE, matches reference
                    float py = y / z;
                    float4 rec = make_float4(px, py, z, __int_as_float(base + k));
                    #pragma unroll
                    for (int q = 0; q < 4; q++) {
                        if (px >= qx0[q & 1] && px <= qx1[q & 1] &&
                            py >= qy0[q >> 1] && py <= qy1[q >> 1]) {
                            int slot = atomicAdd(&s_qcnt[q], 1);
                            if (slot < QCAP) s_quad[q * QCAP + slot] = rec;
                        }
                    }
                }
            }
        }
    }
    __syncthreads();

    // ---- Phase 2: scan own quadrant list, push exact hits per pixel --------
    const int p = tid >> 3;                // pixel 0..63
    const int s = tid & 7;                 // sub-lane 0..7
    const int lx = p & (TILE - 1);
    const int ly = p >> 3;
    const int q  = ((ly >> 2) << 1) | (lx >> 2);
    const float gx = ((float)(tx * TILE + lx) + 0.5f) * (2.0f / W) - 1.0f;
    const float gy = ((float)(ty * TILE + ly) + 0.5f) * (2.0f / H) - 1.0f;
    const float r2 = RADIUS * RADIUS;
    {
        const int qc = min(s_qcnt[q], QCAP);
        for (int j = s; j < qc; j += SPLIT) {
            float4 cd = s_quad[q * QCAP + j];
            float dx = gx - cd.x;
            float dy = gy - cd.y;
            float d2 = dx * dx + dy * dy;
            if (d2 < r2) {                 // exact hit test (matches reference)
                int slot = atomicAdd(&s_pixcnt[p], 1);
                if (slot < PIXCAP) {
                    int o = p * PIXCAP + slot;
                    s_hz[o] = cd.z;
                    s_hd[o] = d2;
                    s_hi[o] = __float_as_int(cd.w);
                }
            }
        }
    }
    __syncthreads();

    // ---- Phase 3: per-pixel top-8 by depth + composite + store (tid<64) ----
    if (tid < PIX) {
        const int pp = tid;
        const int pix_x = tx * TILE + (pp & (TILE - 1));
        const int pix_y = ty * TILE + (pp >> 3);
        const int hc = min(s_pixcnt[pp], PIXCAP);

        float lz[K], ldd[K];
        int   li[K];
        #pragma unroll
        for (int k = 0; k < K; k++) { lz[k] = 3.0e38f; ldd[k] = 0.0f; li[k] = 0; }

        for (int j = 0; j < hc; j++) {
            int o = pp * PIXCAP + j;
            float z = s_hz[o];
            // distinct depths -> top-K set is order-independent (matches top_k)
            if (z < lz[K - 1]) {
                lz[K - 1] = z; ldd[K - 1] = s_hd[o]; li[K - 1] = s_hi[o];
                #pragma unroll
                for (int k = K - 1; k > 0; k--) {
                    if (lz[k] < lz[k - 1]) {
                        float t0 = lz[k];  lz[k]  = lz[k - 1];  lz[k - 1]  = t0;
                        float t1 = ldd[k]; ldd[k] = ldd[k - 1]; ldd[k - 1] = t1;
                        int   t2 = li[k];  li[k]  = li[k - 1];  li[k - 1]  = t2;
                    }
                }
            }
        }

        // front-to-back weights, then batched feature gather (MLP 4 per round)
        float wk[K];
        int   idk[K];
        float T = 1.0f;
        const float inv_r2 = 1.0f / r2;
        #pragma unroll
        for (int k = 0; k < K; k++) {
            bool valid = lz[k] < 1.0e38f;
            float a = 1.0f - ldd[k] * inv_r2;
            a = fminf(fmaxf(a, 0.0f), 1.0f);
            a = valid ? a : 0.0f;
            wk[k]  = a * T;
            idk[k] = valid ? li[k] : 0;
            T *= (1.0f - a);
        }

        float acc[C];
        #pragma unroll
        for (int c2 = 0; c2 < C; c2++) acc[c2] = 0.0f;
        #pragma unroll
        for (int half = 0; half < 2; half++) {
            float4 F0[4], F1[4];
            #pragma unroll
            for (int k = 0; k < 4; k++) {
                const float4* f = (const float4*)(feat + (size_t)idk[half * 4 + k] * C);
                F0[k] = __ldg(&f[0]);
                F1[k] = __ldg(&f[1]);
            }
            #pragma unroll
            for (int k = 0; k < 4; k++) {
                float w = wk[half * 4 + k];
                acc[0] += w * F0[k].x; acc[1] += w * F0[k].y;
                acc[2] += w * F0[k].z; acc[3] += w * F0[k].w;
                acc[4] += w * F1[k].x; acc[5] += w * F1[k].y;
                acc[6] += w * F1[k].z; acc[7] += w * F1[k].w;
            }
        }

        float4* o = (float4*)(out + (size_t)(pix_y * W + pix_x) * C);
        o[0] = make_float4(acc[0], acc[1], acc[2], acc[3]);
        o[1] = make_float4(acc[4], acc[5], acc[6], acc[7]);
    }
}

extern "C" void kernel_launch(void* const* d_in, const int* in_sizes, int n_in,
                              void* d_out, int out_size) {
    const float* pts  = (const float*)d_in[0];   // [B,N,3] f32
    const float* feat = (const float*)d_in[1];   // [B,N,C] f32
    float* out = (float*)d_out;                  // [B,H,W,C] f32
    int n = in_sizes[0] / 3;                     // B=1 -> N
    if (n > MAXN) n = MAXN;

    render_kernel<<<NTILES, TPB>>>(pts, feat, out, n);
}

// round 13
// speedup vs baseline: 1.0903x; 1.0903x over previous
#include <cuda_runtime.h>
#include <cstdint>

// Problem constants (fixed by dataset): B=1, N=4096, C=8, H=W=128, K=8
#define MAXN 8192
constexpr float RADIUS = 0.05f;
constexpr int H = 128, W = 128, C = 8, K = 8;
constexpr int TILE = 8;             // 8x8 pixel tiles
constexpr int TX = W / TILE;        // 16
constexpr int TY = H / TILE;        // 16
constexpr int NTILES = TX * TY;     // 256 CTAs
constexpr int PIX = TILE * TILE;    // 64 pixels per tile
constexpr int SPLIT = 8;            // threads per pixel in scan phase
constexpr int TPB = PIX * SPLIT;    // 512 threads per CTA
constexpr int QCAP = 192;           // per-quadrant cap (mean ~27)
constexpr int PIXCAP = 40;          // per-pixel hit cap (mean ~8)

// smem: quadrant lists 4*192*16 = 12288 B; hit lists 64*40*12 = 30720 B -> 43008 B
constexpr int RAWSZ = 4 * QCAP * 16 + PIX * PIXCAP * 12;

__global__ void __launch_bounds__(TPB)
render_kernel(const float* __restrict__ pts,
              const float* __restrict__ feat,
              float* __restrict__ out, int n) {
    __shared__ __align__(16) unsigned char raw[RAWSZ];
    float4* s_quad = (float4*)raw;                                  // [4][QCAP]
    float*  s_hz   = (float*)(raw + 4 * QCAP * 16);                 // [64][40]
    float*  s_hd   = (float*)(raw + 4 * QCAP * 16 + PIX * PIXCAP * 4);
    int*    s_hi   = (int*)  (raw + 4 * QCAP * 16 + PIX * PIXCAP * 8);
    __shared__ int s_qcnt[4];
    __shared__ int s_pixcnt[PIX];

    const int tile = blockIdx.x;
    const int tx = tile & (TX - 1);
    const int ty = tile >> 4;
    const int tid = threadIdx.x;

    if (tid < PIX) s_pixcnt[tid] = 0;
    if (tid < 4)   s_qcnt[tid] = 0;
    __syncthreads();

    // ---- bboxes over pixel centers, expanded by splat radius + eps (NDC) ----
    const float EPS = 1e-5f;
    const float x0 = ((float)(tx * TILE)            + 0.5f) * (2.0f / W) - 1.0f - RADIUS - EPS;
    const float x1 = ((float)(tx * TILE + TILE - 1) + 0.5f) * (2.0f / W) - 1.0f + RADIUS + EPS;
    const float y0 = ((float)(ty * TILE)            + 0.5f) * (2.0f / H) - 1.0f - RADIUS - EPS;
    const float y1 = ((float)(ty * TILE + TILE - 1) + 0.5f) * (2.0f / H) - 1.0f + RADIUS + EPS;

    float qx0[2], qx1[2], qy0[2], qy1[2];
    #pragma unroll
    for (int hf = 0; hf < 2; hf++) {
        qx0[hf] = ((float)(tx * TILE + hf * 4)     + 0.5f) * (2.0f / W) - 1.0f - RADIUS - EPS;
        qx1[hf] = ((float)(tx * TILE + hf * 4 + 3) + 0.5f) * (2.0f / W) - 1.0f + RADIUS + EPS;
        qy0[hf] = ((float)(ty * TILE + hf * 4)     + 0.5f) * (2.0f / H) - 1.0f - RADIUS - EPS;
        qy1[hf] = ((float)(ty * TILE + hf * 4 + 3) + 0.5f) * (2.0f / H) - 1.0f + RADIUS + EPS;
    }

    // ---- Phase 1: cull all points vs tile bbox (division-free), coalesced
    //      scalar loads (R10-proven; vectorized loads regressed in R12) ------
    #pragma unroll
    for (int it = 0; it < MAXN / TPB; it++) {
        int i = it * TPB + tid;
        if (i < n) {
            float x = pts[3 * i + 0];
            float y = pts[3 * i + 1];
            float z = pts[3 * i + 2];
            // z>0: x/z >= x0  <=>  x >= x0*z  (conservative; exact test later)
            bool hit = (z > 0.0f) &&
                       (x >= x0 * z) && (x <= x1 * z) &&
                       (y >= y0 * z) && (y <= y1 * z);
            if (hit) {
                float px = x / z;          // exact IEEE, matches reference
                float py = y / z;
                float4 rec = make_float4(px, py, z, __int_as_float(i));
                #pragma unroll
                for (int q = 0; q < 4; q++) {
                    if (px >= qx0[q & 1] && px <= qx1[q & 1] &&
                        py >= qy0[q >> 1] && py <= qy1[q >> 1]) {
                        int slot = atomicAdd(&s_qcnt[q], 1);
                        if (slot < QCAP) s_quad[q * QCAP + slot] = rec;
                    }
                }
            }
        }
    }
    __syncthreads();

    // ---- Phase 2: scan own quadrant list, push exact hits per pixel --------
    const int p = tid >> 3;                // pixel 0..63
    const int s = tid & 7;                 // sub-lane 0..7
    const int lx = p & (TILE - 1);
    const int ly = p >> 3;
    const int q  = ((ly >> 2) << 1) | (lx >> 2);
    const float gx = ((float)(tx * TILE + lx) + 0.5f) * (2.0f / W) - 1.0f;
    const float gy = ((float)(ty * TILE + ly) + 0.5f) * (2.0f / H) - 1.0f;
    const float r2 = RADIUS * RADIUS;
    {
        const int qc = min(s_qcnt[q], QCAP);
        for (int j = s; j < qc; j += SPLIT) {
            float4 cd = s_quad[q * QCAP + j];
            float dx = gx - cd.x;
            float dy = gy - cd.y;
            float d2 = dx * dx + dy * dy;
            if (d2 < r2) {                 // exact hit test (matches reference)
                int slot = atomicAdd(&s_pixcnt[p], 1);
                if (slot < PIXCAP) {
                    int o = p * PIXCAP + slot;
                    s_hz[o] = cd.z;
                    s_hd[o] = d2;
                    s_hi[o] = __float_as_int(cd.w);
                }
            }
        }
    }
    __syncthreads();

    // ---- Phase 3: 2 threads per pixel (channel halves), tid < 128 ----------
    // Both threads of a pixel duplicate the cheap top-8 insert + weights
    // (registers only, no communication); each gathers its half's 8 float4s
    // in ONE parallel L2 round and writes its own float4.
    if (tid < 2 * PIX) {
        const int pp = tid >> 1;           // pixel 0..63
        const int hf = tid & 1;            // channel half 0..1
        const int pix_x = tx * TILE + (pp & (TILE - 1));
        const int pix_y = ty * TILE + (pp >> 3);
        const int hc = min(s_pixcnt[pp], PIXCAP);

        float lz[K], ldd[K];
        int   li[K];
        #pragma unroll
        for (int k = 0; k < K; k++) { lz[k] = 3.0e38f; ldd[k] = 0.0f; li[k] = 0; }

        for (int j = 0; j < hc; j++) {
            int o = pp * PIXCAP + j;
            float z = s_hz[o];
            // distinct depths -> top-K set is order-independent (matches top_k)
            if (z < lz[K - 1]) {
                lz[K - 1] = z; ldd[K - 1] = s_hd[o]; li[K - 1] = s_hi[o];
                #pragma unroll
                for (int k = K - 1; k > 0; k--) {
                    if (lz[k] < lz[k - 1]) {
                        float t0 = lz[k];  lz[k]  = lz[k - 1];  lz[k - 1]  = t0;
                        float t1 = ldd[k]; ldd[k] = ldd[k - 1]; ldd[k - 1] = t1;
                        int   t2 = li[k];  li[k]  = li[k - 1];  li[k - 1]  = t2;
                    }
                }
            }
        }

        // front-to-back weights (same serial order as reference cumprod)
        float wk[K];
        int   idk[K];
        float T = 1.0f;
        const float inv_r2 = 1.0f / r2;
        #pragma unroll
        for (int k = 0; k < K; k++) {
            bool valid = lz[k] < 1.0e38f;
            float a = 1.0f - ldd[k] * inv_r2;
            a = fminf(fmaxf(a, 0.0f), 1.0f);
            a = valid ? a : 0.0f;
            wk[k]  = a * T;
            idk[k] = valid ? li[k] : 0;
            T *= (1.0f - a);
        }

        // this thread's half: 8 independent loads, one latency round
        float4 F[K];
        #pragma unroll
        for (int k = 0; k < K; k++) {
            const float4* f = (const float4*)(feat + (size_t)idk[k] * C);
            F[k] = __ldg(&f[hf]);
        }
        float a0 = 0.0f, a1 = 0.0f, a2 = 0.0f, a3 = 0.0f;
        #pragma unroll
        for (int k = 0; k < K; k++) {
            a0 += wk[k] * F[k].x;
            a1 += wk[k] * F[k].y;
            a2 += wk[k] * F[k].z;
            a3 += wk[k] * F[k].w;
        }

        float4* o = (float4*)(out + (size_t)(pix_y * W + pix_x) * C);
        o[hf] = make_float4(a0, a1, a2, a3);
    }
}

extern "C" void kernel_launch(void* const* d_in, const int* in_sizes, int n_in,
                              void* d_out, int out_size) {
    const float* pts  = (const float*)d_in[0];   // [B,N,3] f32
    const float* feat = (const float*)d_in[1];   // [B,N,C] f32
    float* out = (float*)d_out;                  // [B,H,W,C] f32
    int n = in_sizes[0] / 3;                     // B=1 -> N
    if (n > MAXN) n = MAXN;

    render_kernel<<<NTILES, TPB>>>(pts, feat, out, n);
}